// round 8
// baseline (speedup 1.0000x reference)
#include <cuda_runtime.h>

// ---------------- problem constants ----------------
#define MB    32
#define DCH   256
#define SSP   3136
#define NGRP  16
#define GS    16
#define NSAMP (MB*SSP)    // 100352
#define EPSV  1e-6f

// stats tiling: 112-sample tiles, 28 per image, 896 per group
#define STILE     112
#define TPI_S     (SSP/STILE)             // 28
#define STAT_TPB  7                       // tiles per block
#define STAT_BLKX (MB*TPI_S/STAT_TPB)     // 128 blocks per group
#define SPAD      116                     // padded row stride (464B, 16B-aligned)

// whiten tiling: warp owns 2 rows; 32 lanes = 32 pairs; 8 its of 32 pairs
#define HSSP      (SSP/2)                 // 1568 pairs per image per channel
#define PPG       (NSAMP/2)               // 50176 pairs per group
#define WHT_IT    8
#define WHT_BLKX  (PPG/(WHT_IT*32))       // 196 blocks per group

typedef unsigned long long ULL;

// ---------------- scratch ----------------
__device__ float  g_P[NGRP][GS][GS];      // raw product sums (upper blocks valid)
__device__ float  g_S[NGRP][GS];          // raw channel sums
__device__ float2 g_W2[NGRP][GS][GS];     // whitening matrix packed (w,w)
__device__ float  g_bias[NGRP][GS];       // -W @ mu

// ---------------- f32x2 helpers ----------------
__device__ __forceinline__ ULL ffma2(ULL a, ULL b, ULL c) {
    ULL d;
    asm("fma.rn.f32x2 %0, %1, %2, %3;" : "=l"(d) : "l"(a), "l"(b), "l"(c));
    return d;
}
__device__ __forceinline__ ULL addf2(ULL a, ULL b) {
    ULL d;
    asm("add.rn.f32x2 %0, %1, %2;" : "=l"(d) : "l"(a), "l"(b));
    return d;
}
__device__ __forceinline__ ULL pack2(float lo, float hi) {
    ULL r;
    asm("mov.b64 %0, {%1, %2};" : "=l"(r) : "f"(lo), "f"(hi));
    return r;
}
__device__ __forceinline__ void unpack2(ULL v, float& lo, float& hi) {
    asm("mov.b64 {%0, %1}, %2;" : "=f"(lo), "=f"(hi) : "l"(v));
}

// ---------------- kernel 0: zero accumulators ----------------
__global__ void zero_kernel() {
    int tid = blockIdx.x * 256 + threadIdx.x;
    if (tid < NGRP * GS * GS) ((float*)g_P)[tid] = 0.0f;
    if (tid < NGRP * GS)      ((float*)g_S)[tid] = 0.0f;
}

// ---------------- kernel 1: stats, symmetric (upper-tri) warp blocking --------
// 320 threads = 10 warps; warp w owns 4x4 block (ti,tj), ti<=tj, of the 16x16
// Gram matrix. Lanes = sample pairs. Tile 16ch x 112 samples, double-buffered.
__global__ __launch_bounds__(320) void stats_kernel(const float* __restrict__ x) {
    __shared__ float sm[2][GS][SPAD];

    const int g    = blockIdx.y;
    const int tid  = threadIdx.x;
    const int wid  = tid >> 5;
    const int lane = tid & 31;

    // upper-triangle enumeration of 4x4 blocks
    int ti, tj;
    if      (wid < 4) { ti = 0; tj = wid;     }
    else if (wid < 7) { ti = 1; tj = wid - 3; }
    else if (wid < 9) { ti = 2; tj = wid - 5; }
    else              { ti = 3; tj = 3;       }
    const bool diag = (ti == tj);

    ULL acc[4][4];
#pragma unroll
    for (int r = 0; r < 4; r++)
#pragma unroll
        for (int c = 0; c < 4; c++) acc[r][c] = 0ull;
    ULL accs[4];
#pragma unroll
    for (int r = 0; r < 4; r++) accs[r] = 0ull;
    const ULL one2 = pack2(1.0f, 1.0f);

    const size_t gbase = (size_t)g * GS * SSP;

    auto tile_off = [&](int tt) -> size_t {
        const int tileId = blockIdx.x * STAT_TPB + tt;
        const int b  = tileId / TPI_S;
        const int s0 = (tileId - b * TPI_S) * STILE;
        return (size_t)b * DCH * SSP + gbase + s0;
    };

    // staging: 448 float4 per tile; thread covers idx=tid (<448 always) and
    // idx=tid+320 (only tid<128)
    const int r0 = tid / 28,          c0 = tid - r0 * 28;
    const int i1 = tid + 320;
    const int r1 = i1 / 28,           c1 = i1 - r1 * 28;
    const bool has2 = (tid < 128);

    // prefetch tile 0
    size_t off = tile_off(0);
    float4 p0 = *(const float4*)(x + off + (size_t)r0 * SSP + 4 * c0);
    float4 p1 = has2 ? *(const float4*)(x + off + (size_t)r1 * SSP + 4 * c1)
                     : make_float4(0, 0, 0, 0);

    for (int tt = 0; tt < STAT_TPB; tt++) {
        const int buf = tt & 1;
        *(float4*)&sm[buf][r0][4 * c0] = p0;
        if (has2) *(float4*)&sm[buf][r1][4 * c1] = p1;
        __syncthreads();

        if (tt + 1 < STAT_TPB) {
            size_t noff = tile_off(tt + 1);
            p0 = *(const float4*)(x + noff + (size_t)r0 * SSP + 4 * c0);
            if (has2) p1 = *(const float4*)(x + noff + (size_t)r1 * SSP + 4 * c1);
        }

        // compute: 56 pairs; pp=0 lanes 0-31, pp=1 lanes 0-23
#pragma unroll
        for (int pp = 0; pp < 2; pp++) {
            const int lane2 = lane + 32 * pp;
            if (pp == 0 || lane < 24) {
                const int t = 2 * lane2;
                ULL xi[4], xj[4];
#pragma unroll
                for (int r = 0; r < 4; r++)
                    xi[r] = *(const ULL*)&sm[buf][ti * 4 + r][t];
#pragma unroll
                for (int c = 0; c < 4; c++)
                    xj[c] = *(const ULL*)&sm[buf][tj * 4 + c][t];
#pragma unroll
                for (int r = 0; r < 4; r++)
#pragma unroll
                    for (int c = 0; c < 4; c++)
                        acc[r][c] = ffma2(xi[r], xj[c], acc[r][c]);
                if (diag) {
#pragma unroll
                    for (int r = 0; r < 4; r++)
                        accs[r] = ffma2(xi[r], one2, accs[r]);
                }
            }
        }
        __syncthreads();
    }

    // warp butterfly reduction (packed), then lane 0 -> global atomics
#pragma unroll
    for (int r = 0; r < 4; r++)
#pragma unroll
        for (int c = 0; c < 4; c++) {
            ULL v = acc[r][c];
#pragma unroll
            for (int m = 16; m >= 1; m >>= 1)
                v = addf2(v, __shfl_xor_sync(0xffffffffu, v, m));
            if (lane == 0) {
                float lo, hi;
                unpack2(v, lo, hi);
                atomicAdd(&g_P[g][ti * 4 + r][tj * 4 + c], lo + hi);
            }
        }
    if (diag) {
#pragma unroll
        for (int r = 0; r < 4; r++) {
            ULL v = accs[r];
#pragma unroll
            for (int m = 16; m >= 1; m >>= 1)
                v = addf2(v, __shfl_xor_sync(0xffffffffu, v, m));
            if (lane == 0) {
                float lo, hi;
                unpack2(v, lo, hi);
                atomicAdd(&g_S[g][ti * 4 + r], lo + hi);
            }
        }
    }
}

// ---------------- kernel 2: sigma -> Cholesky -> inv(T) (one warp/group) ------
__global__ void solve_kernel() {
    __shared__ float A[NGRP][GS][GS + 1];
    __shared__ float Wm[NGRP][GS][GS + 1];
    __shared__ float mu[NGRP][GS];

    const int g    = threadIdx.x >> 5;
    const int lane = threadIdx.x & 31;

    const float invn  = 1.0f / (float)NSAMP;
    const float scale = (1.0f - EPSV) / (float)(NSAMP - 1);

    if (lane < GS) mu[g][lane] = g_S[g][lane] * invn;
    __syncwarp();

    if (lane < GS) {
        const int j = lane;
        const float muj = mu[g][j];
        for (int i = 0; i < GS; i++) {
            // symmetric fetch: only upper 4x4 blocks were accumulated
            float pij = ((i >> 2) <= (j >> 2)) ? g_P[g][i][j] : g_P[g][j][i];
            float v = (pij - (float)NSAMP * mu[g][i] * muj) * scale;
            if (i == j) v += EPSV;
            A[g][i][j] = v;
        }
    }
    __syncwarp();

    for (int k = 0; k < GS; k++) {
        float s = 0.0f;
        if (lane < GS && lane >= k) {
            s = A[g][lane][k];
            for (int p = 0; p < k; p++) s -= A[g][lane][p] * A[g][k][p];
        }
        float d = __shfl_sync(0xffffffffu, s, k);
        d = sqrtf(d);
        if (lane < GS && lane >= k)
            A[g][lane][k] = (lane == k) ? d : s / d;
        __syncwarp();
    }

    if (lane < GS) {
        const int c = lane;
        for (int r = 0; r < GS; r++) Wm[g][r][c] = 0.0f;
        Wm[g][c][c] = 1.0f / A[g][c][c];
        for (int r = c + 1; r < GS; r++) {
            float t = 0.0f;
            for (int p = c; p < r; p++) t += A[g][r][p] * Wm[g][p][c];
            Wm[g][r][c] = -t / A[g][r][r];
        }
    }
    __syncwarp();

    if (lane < GS) {
        const int i = lane;
        float bias = 0.0f;
        for (int j = 0; j < GS; j++) {
            float w = Wm[g][i][j];
            bias -= w * mu[g][j];
            g_W2[g][i][j] = make_float2(w, w);
        }
        g_bias[g][i] = bias;
    }
}

// ---------------- kernel 3: whiten, warp-owns-2-rows ---------------------------
// 256 threads = 8 warps; warp (rp) owns output rows 2rp, 2rp+1 with W in regs
// (loaded once). Lanes = 32 consecutive pairs: all gmem traffic is 256B
// coalesced; the 8 warps re-read the same x lines -> L1 hits.
__global__ __launch_bounds__(256) void whiten_kernel(const float* __restrict__ x,
                                                     float* __restrict__ out) {
    const int g    = blockIdx.y;
    const int tid  = threadIdx.x;
    const int rp   = tid >> 5;        // row-pair 0..7
    const int pq   = tid & 31;        // pair lane
    const int i0   = 2 * rp;
    const int i1   = 2 * rp + 1;

    ULL w0[GS], w1[GS];
#pragma unroll
    for (int j = 0; j < GS; j++) {
        w0[j] = *(const ULL*)&g_W2[g][i0][j];
        w1[j] = *(const ULL*)&g_W2[g][i1][j];
    }
    const float bb0 = g_bias[g][i0];
    const float bb1 = g_bias[g][i1];
    const ULL b0 = pack2(bb0, bb0);
    const ULL b1 = pack2(bb1, bb1);

    const size_t gbase = (size_t)g * GS * SSP;

#pragma unroll 1
    for (int it = 0; it < WHT_IT; it++) {
        const int P  = blockIdx.x * (WHT_IT * 32) + it * 32 + pq;
        const int b  = P / HSSP;
        const int pr = P - b * HSSP;
        const float* base  = x   + (size_t)b * DCH * SSP + gbase + 2 * pr;
        float*       obase = out + (size_t)b * DCH * SSP + gbase + 2 * pr;

        ULL in[GS];
#pragma unroll
        for (int j = 0; j < GS; j++)
            in[j] = *(const ULL*)(base + (size_t)j * SSP);

        ULL a0 = b0, a1 = b1;
#pragma unroll
        for (int j = 0; j < GS; j++) {
            a0 = ffma2(w0[j], in[j], a0);
            a1 = ffma2(w1[j], in[j], a1);
        }
        *(ULL*)(obase + (size_t)i0 * SSP) = a0;
        *(ULL*)(obase + (size_t)i1 * SSP) = a1;
    }
}

// ---------------- launch ----------------
extern "C" void kernel_launch(void* const* d_in, const int* in_sizes, int n_in,
                              void* d_out, int out_size) {
    const float* x = (const float*)d_in[0];
    float* out = (float*)d_out;

    zero_kernel<<<16, 256>>>();

    dim3 sgrid(STAT_BLKX, NGRP);           // 128 x 16 = 2048 blocks, 320 thr
    stats_kernel<<<sgrid, 320>>>(x);

    solve_kernel<<<1, 512>>>();            // one warp per group

    dim3 wgrid(WHT_BLKX, NGRP);            // 196 x 16 = 3136 blocks, 256 thr
    whiten_kernel<<<wgrid, 256>>>(x, out);
}